// round 16
// baseline (speedup 1.0000x reference)
#include <cuda_runtime.h>
#include <cuda_bf16.h>
#include <cstdint>
#include <cstddef>

// DecorrelationGradient: out = 0.5 * (X^T X)/N - 0.5   (KAPPA = 0.5 algebraic collapse)
// X: [16384, 768] fp32.  out: [768, 768] fp32.
//
// R16 (from R14 base): (a) cvt uses default-caching loads so x stays L2-resident
// across graph replays (was __ldcs -> forced DRAM), (b) mirror writes moved out
// of gram's epilogue into a small post-pass transpose kernel (kills 4.6M scalar
// REDs in gram), (c) folded out=-0.5 init kept in cvt.
// gram: bf16 SYRK, CTA 96x96, 6 warps (2m x 3n), warp tile 48x32, split-K=16,
// direct-region red2 epilogue only.

#define D        768
#define NROW     16384
#define BT       96
#define NT       8
#define NTILES   36                     // NT*(NT+1)/2
#define NPAIRS   28                     // off-diagonal pairs (I<J)
#define NSPLIT   16
#define KCH      32                     // k samples per pipeline chunk
#define KSB      208                    // smem row stride: 96 m * 2B + 16B pad
#define TILE_B   (KCH * KSB)            // 6656
#define STAGE_B  (2 * TILE_B)           // 13312
#define NSTAGE   3
#define DYN_SMEM (NSTAGE * STAGE_B)     // 39936
#define OUT4     (D * D / 4)            // 147456 float4 in out

__device__ __align__(16) __nv_bfloat16 g_xb[(size_t)NROW * D];   // 24 MB bf16 copy of X

__device__ __forceinline__ uint32_t saddr(const void* p) {
    return (uint32_t)__cvta_generic_to_shared(p);
}
__device__ __forceinline__ void cp16(uint32_t s, const void* g) {
    asm volatile("cp.async.cg.shared.global [%0], [%1], 16;" :: "r"(s), "l"(g));
}
__device__ __forceinline__ void red2(float* p, float a, float b) {
    asm volatile("red.global.add.v2.f32 [%0], {%1, %2};" :: "l"(p), "f"(a), "f"(b) : "memory");
}

#define LDMX4T(R, A) \
    asm volatile("ldmatrix.sync.aligned.m8n8.x4.trans.shared.b16 {%0,%1,%2,%3}, [%4];" \
        : "=r"((R)[0]), "=r"((R)[1]), "=r"((R)[2]), "=r"((R)[3]) : "r"(A))

#define MMA16816(C, A, B0, B1) \
    asm volatile("mma.sync.aligned.m16n8k16.row.col.f32.bf16.bf16.f32 " \
        "{%0,%1,%2,%3}, {%4,%5,%6,%7}, {%8,%9}, {%0,%1,%2,%3};" \
        : "+f"((C)[0]), "+f"((C)[1]), "+f"((C)[2]), "+f"((C)[3]) \
        : "r"((A)[0]), "r"((A)[1]), "r"((A)[2]), "r"((A)[3]), "r"(B0), "r"(B1))

// ---------------------------------------------------------------------------
// 1) Streaming convert + out init.  Default caching: x stays L2-resident
//    across graph replays (x 48MB + xb 24MB + out 2.3MB < 126MB L2).
// ---------------------------------------------------------------------------
__global__ void __launch_bounds__(256)
cvt_kernel(const float* __restrict__ x, float4* __restrict__ out4) {
    int t = blockIdx.x * 256 + threadIdx.x;
    if (t < OUT4)
        out4[t] = make_float4(-0.5f, -0.5f, -0.5f, -0.5f);

    size_t i = (size_t)t * 16;
    float4 v[4];
#pragma unroll
    for (int j = 0; j < 4; j++) v[j] = *(const float4*)(x + i + 4 * j);
#pragma unroll
    for (int j = 0; j < 4; j += 2) {
        union { __nv_bfloat162 h2[4]; uint4 u; } p;
        p.h2[0] = __floats2bfloat162_rn(v[j].x, v[j].y);
        p.h2[1] = __floats2bfloat162_rn(v[j].z, v[j].w);
        p.h2[2] = __floats2bfloat162_rn(v[j + 1].x, v[j + 1].y);
        p.h2[3] = __floats2bfloat162_rn(v[j + 1].z, v[j + 1].w);
        *(uint4*)(g_xb + i + 4 * j) = p.u;
    }
}

// ---------------------------------------------------------------------------
// 2) bf16 SYRK: 96x96 tiles, 6 warps (2m x 3n), 48x32 per warp.
//    smem tile layout: [k][m], 32 k-rows of 96 bf16 (192B data + 16B pad).
//    One tile = 32 rows x 12 chunks = 384 16B chunks; 192 threads -> 2 iters.
// ---------------------------------------------------------------------------
__device__ __forceinline__ void load_chunk(uint32_t sA, int k0,
                                           int colA, int colB,
                                           bool diag, int tid) {
#pragma unroll
    for (int i = 0; i < 2; i++) {
        int idx = tid + i * 192;        // 0..383
        int k   = idx / 12;             // 0..31
        int ch  = idx % 12;             // 16B chunk in the 192B row
        uint32_t dst = (uint32_t)k * KSB + (uint32_t)ch * 16;
        const __nv_bfloat16* g = g_xb + (size_t)(k0 + k) * D + ch * 8;
        cp16(sA + dst, g + colA);
        if (!diag) cp16(sA + TILE_B + dst, g + colB);
    }
    asm volatile("cp.async.commit_group;" ::: "memory");
}

extern __shared__ char dyn_smem[];

__global__ void __launch_bounds__(192, 4)
gram_bf16(float* __restrict__ out, int nchunks_total, float hscale) {
    int bx = blockIdx.x;
    int tile = bx % NTILES, split = bx / NTILES;
    int I = 0, t = tile;
    while (t >= NT - I) { t -= NT - I; I++; }
    int J = I + t;
    bool diag = (I == J);
    int colA = I * BT, colB = J * BT;

    int c0 = split * nchunks_total / NSPLIT;
    int c1 = (split + 1) * nchunks_total / NSPLIT;
    int nch = c1 - c0;

    int tid = threadIdx.x, lane = tid & 31, warp = tid >> 5;
    int wm = warp & 1, wn = warp >> 1;       // 2m x 3n
    int r = lane & 7, sel = lane >> 3;
    uint32_t sbase = saddr(dyn_smem);

    // ldmatrix.x4.trans per-lane offsets (within a tile buffer)
    uint32_t aoff = (uint32_t)((sel >> 1) * 8 + r) * KSB +
                    (uint32_t)(wm * 48 + (sel & 1) * 8) * 2;
    uint32_t boff = (uint32_t)((sel & 1) * 8 + r) * KSB +
                    (uint32_t)(wn * 32 + (sel >> 1) * 8) * 2;

    float c[3][4][4];
#pragma unroll
    for (int mi = 0; mi < 3; mi++)
#pragma unroll
        for (int ni = 0; ni < 4; ni++)
#pragma unroll
            for (int q = 0; q < 4; q++) c[mi][ni][q] = 0.0f;

    // prologue: 2 chunks in flight
    load_chunk(sbase,           (c0 + 0) * KCH, colA, colB, diag, tid);
    load_chunk(sbase + STAGE_B, (c0 + 1) * KCH, colA, colB, diag, tid);

    for (int ch = 0; ch < nch; ch++) {
        if (ch < nch - 1) asm volatile("cp.async.wait_group 1;" ::: "memory");
        else              asm volatile("cp.async.wait_group 0;" ::: "memory");
        __syncthreads();
        // prefetch 2 ahead into slot (ch+2)%3 (chunk ch-1 fully consumed)
        int nxt = ch + 2;
        if (nxt < nch)
            load_chunk(sbase + (nxt % NSTAGE) * STAGE_B, (c0 + nxt) * KCH,
                       colA, colB, diag, tid);

        uint32_t sA = sbase + (ch % NSTAGE) * STAGE_B;
        uint32_t sB = diag ? sA : sA + TILE_B;

#pragma unroll
        for (int step = 0; step < KCH / 16; step++) {
            uint32_t kb = (uint32_t)step * (16 * KSB);
            uint32_t a[3][4];
#pragma unroll
            for (int mi = 0; mi < 3; mi++)
                LDMX4T(a[mi], sA + kb + aoff + mi * 32);        // +16 m = +32B
            uint32_t b[2][4];
#pragma unroll
            for (int p = 0; p < 2; p++)
                LDMX4T(b[p], sB + kb + boff + p * 32);          // +16 n = +32B
#pragma unroll
            for (int mi = 0; mi < 3; mi++)
#pragma unroll
                for (int ni = 0; ni < 4; ni++) {
                    uint32_t* bp = b[ni >> 1];
                    if (ni & 1) MMA16816(c[mi][ni], a[mi], bp[2], bp[3]);
                    else        MMA16816(c[mi][ni], a[mi], bp[0], bp[1]);
                }
        }
    }

    // epilogue: scale + RED into out, DIRECT region only (mirror is a post-pass)
    int mw = I * BT + wm * 48 + (lane >> 2);
    int nw = J * BT + wn * 32 + 2 * (lane & 3);

#pragma unroll
    for (int mi = 0; mi < 3; mi++) {
        int m = mw + mi * 16;
#pragma unroll
        for (int ni = 0; ni < 4; ni++) {
            int n = nw + ni * 8;
            red2(&out[(size_t)m * D + n],
                 hscale * c[mi][ni][0], hscale * c[mi][ni][1]);
            red2(&out[(size_t)(m + 8) * D + n],
                 hscale * c[mi][ni][2], hscale * c[mi][ni][3]);
        }
    }
}

// ---------------------------------------------------------------------------
// 3) Mirror: copy the 28 off-diagonal 96x96 blocks to their transposes.
//    One 32x32 smem-transpose block per (pair, 3x3 subtile): 252 blocks.
// ---------------------------------------------------------------------------
__global__ void __launch_bounds__(256)
mirror_kernel(float* __restrict__ out) {
    int pair = blockIdx.x / 9, st = blockIdx.x % 9;
    // pair -> (I,J), I<J
    int I = 0, t = pair;
    while (t >= NT - 1 - I) { t -= NT - 1 - I; I++; }
    int J = I + 1 + t;

    int sr0 = I * BT + (st / 3) * 32;    // source rows (I block)
    int sc0 = J * BT + (st % 3) * 32;    // source cols (J block)

    __shared__ float s[32][33];
    int tx = threadIdx.x & 31, ty = threadIdx.x >> 5;   // 32 x 8
#pragma unroll
    for (int i = 0; i < 32; i += 8)
        s[ty + i][tx] = out[(size_t)(sr0 + ty + i) * D + sc0 + tx];
    __syncthreads();
#pragma unroll
    for (int i = 0; i < 32; i += 8)
        out[(size_t)(sc0 + ty + i) * D + sr0 + tx] = s[tx][ty + i];
}

extern "C" void kernel_launch(void* const* d_in, const int* in_sizes, int n_in,
                              void* d_out, int out_size) {
    const float* x = (const float*)d_in[0];
    float* out = (float*)d_out;
    int N = in_sizes[0] / D;            // 16384
    int nchunks = N / KCH;              // 512

    int nelem = N * D;                  // 12,582,912
    cvt_kernel<<<nelem / (256 * 16), 256>>>(x, (float4*)out);

    cudaFuncSetAttribute(gram_bf16, cudaFuncAttributeMaxDynamicSharedMemorySize,
                         DYN_SMEM);
    gram_bf16<<<NTILES * NSPLIT, 192, DYN_SMEM>>>(out, nchunks, 0.5f / (float)N);

    mirror_kernel<<<NPAIRS * 9, 256>>>(out);
}